// round 16
// baseline (speedup 1.0000x reference)
#include <cuda_runtime.h>
#include <cuda_bf16.h>

// TimeFeatureEmbedding: y = x @ W^T + b  ([B,T,4] x [512,4] -> [B,T,512]),
// broadcast each (b,t) row S times -> [B,T,S,512].  402.7 MB pure store
// stream; compute is 16 FMA/thread — strictly DRAM-write-bound.
//
// CONVERGED CONFIG (best 57.47us): grid = BT*4 (split=4), 256 threads/CTA,
// 8 STG.128/thread of one register-resident float4, __stcs streaming
// stores, every warp store 512B contiguous. 7.13 TB/s effective writes —
// at the measured path-independent LTS write ceiling.
//
// This round's only change: fully unroll the 8-iteration store loop
// (was unroll 4) -> all 8 independent STG.128 front-batched straight-line,
// deeper store MLP, one fewer branch, shorter per-CTA span.
//
// Probed and rejected R5-R13: persistent grid (68.1), split 1/2/8 and
// 128-thr CTAs (61.5/59.9/75.8/62.2), two-phase Y precompute (60.9),
// L2 residency via __stcs/__stwt splits (59.3/59.4 — no retention).

__global__ __launch_bounds__(256, 8)
void tfe_broadcast_kernel(const float* __restrict__ x,
                          const float* __restrict__ W,
                          const float* __restrict__ b,
                          float* __restrict__ out,
                          int S, int split_shift)
{
    const int bt   = blockIdx.x >> split_shift;              // (b,t) row
    const int part = blockIdx.x & ((1 << split_shift) - 1);  // slice of S repeats
    const int tid  = threadIdx.x;
    const int d4   = tid & 127;              // float4 index within D_MODEL=512

    // x row: 4 floats broadcast across the CTA (L1/L2-hot after first wave)
    const float4 x4 = __ldg(reinterpret_cast<const float4*>(x) + bt);

    // bias + W slice for this thread's 4 output dims
    const float4 b4 = __ldg(reinterpret_cast<const float4*>(b) + d4);
    const float4* W4 = reinterpret_cast<const float4*>(W);
    const float4 w0 = __ldg(W4 + d4 * 4 + 0);
    const float4 w1 = __ldg(W4 + d4 * 4 + 1);
    const float4 w2 = __ldg(W4 + d4 * 4 + 2);
    const float4 w3 = __ldg(W4 + d4 * 4 + 3);

    float4 y4;
    y4.x = fmaf(x4.x, w0.x, fmaf(x4.y, w0.y, fmaf(x4.z, w0.z, fmaf(x4.w, w0.w, b4.x))));
    y4.y = fmaf(x4.x, w1.x, fmaf(x4.y, w1.y, fmaf(x4.z, w1.z, fmaf(x4.w, w1.w, b4.y))));
    y4.z = fmaf(x4.x, w2.x, fmaf(x4.y, w2.y, fmaf(x4.z, w2.z, fmaf(x4.w, w2.w, b4.z))));
    y4.w = fmaf(x4.x, w3.x, fmaf(x4.y, w3.y, fmaf(x4.z, w3.z, fmaf(x4.w, w3.w, b4.w))));

    // Slice: (S >> split_shift) * 128 float4, contiguous, 256-aligned start
    // (launcher guarantees S >> shift is even -> slice length multiple of
    // 256). Hence (i & 127) == d4 on every iteration: the same register-
    // resident float4 is streamed; each warp store is 512B contiguous.
    const int slice4 = (S >> split_shift) * 128;
    float4* out4 = reinterpret_cast<float4*>(out)
                 + (size_t)bt * (size_t)S * 128u
                 + (size_t)part * (size_t)slice4;

    // Full unroll: 8 iterations at S=64/shift=2 -> straight-line burst of
    // 8 independent STG.128 (max store MLP, no loop-carried branch).
    #pragma unroll 8
    for (int i = tid; i < slice4; i += 256) {
        __stcs(out4 + i, y4);   // evict-first streaming store
    }
}

extern "C" void kernel_launch(void* const* d_in, const int* in_sizes, int n_in,
                              void* d_out, int out_size)
{
    // Inputs: x [B,T,4] f32, S (scalar), W [512,4] f32, b [512] f32.
    const float* x = (const float*)d_in[0];
    const float* W = (const float*)d_in[2];
    const float* b = (const float*)d_in[3];
    float* out = (float*)d_out;

    const int BT = in_sizes[0] / 4;          // B*T rows (d_inp = 4)
    const int S  = out_size / (BT * 512);    // recover S arithmetically

    // split=4 when S/4 is even (preserves the 256-float4 alignment
    // invariant); degrade gracefully otherwise. S=64 -> shift=2, grid 12288.
    int shift = 0;
    if      ((S % 8) == 0) shift = 2;
    else if ((S % 4) == 0) shift = 1;

    tfe_broadcast_kernel<<<BT << shift, 256>>>(x, W, b, out, S, shift);
}

// round 17
// speedup vs baseline: 1.0406x; 1.0406x over previous
#include <cuda_runtime.h>
#include <cuda_bf16.h>

// TimeFeatureEmbedding: y = x @ W^T + b  ([B,T,4] x [512,4] -> [B,T,512]),
// broadcast each (b,t) row S times -> [B,T,S,512].  402.7 MB pure store
// stream; compute is 16 FMA/thread — strictly DRAM-write-bound.
//
// FINAL (converged, best 57.47us): grid = BT*4 (split=4), 256 threads/CTA,
// 8 STG.128/thread of one register-resident float4, __stcs streaming
// stores, unroll 4 (two paced batches), every warp store 512B contiguous.
// 7.13 TB/s effective writes — at the path-independent LTS write ceiling.
//
// Every neighboring config measured and rejected:
//  R5  persistent 1-wave grid:        68.1us (straggler-bound)
//  R2/R6/R8/R9 split 1/2/8 variants:  61.5 / 59.9 / 75.8 / 62.2us
//  R10 two-phase Y precompute:        60.9us (loads never limited)
//  R12/R13 L2 residency hint splits:  59.3 / 59.4us (no cross-replay retention)
//  R15 full unroll 8:                 59.8us (store-burst -> L1tex queue
//      contention -> larger cross-CTA spread; unroll 4 paces the queue)

__global__ __launch_bounds__(256, 8)
void tfe_broadcast_kernel(const float* __restrict__ x,
                          const float* __restrict__ W,
                          const float* __restrict__ b,
                          float* __restrict__ out,
                          int S, int split_shift)
{
    const int bt   = blockIdx.x >> split_shift;              // (b,t) row
    const int part = blockIdx.x & ((1 << split_shift) - 1);  // slice of S repeats
    const int tid  = threadIdx.x;
    const int d4   = tid & 127;              // float4 index within D_MODEL=512

    // x row: 4 floats broadcast across the CTA (L1/L2-hot after first wave)
    const float4 x4 = __ldg(reinterpret_cast<const float4*>(x) + bt);

    // bias + W slice for this thread's 4 output dims
    const float4 b4 = __ldg(reinterpret_cast<const float4*>(b) + d4);
    const float4* W4 = reinterpret_cast<const float4*>(W);
    const float4 w0 = __ldg(W4 + d4 * 4 + 0);
    const float4 w1 = __ldg(W4 + d4 * 4 + 1);
    const float4 w2 = __ldg(W4 + d4 * 4 + 2);
    const float4 w3 = __ldg(W4 + d4 * 4 + 3);

    float4 y4;
    y4.x = fmaf(x4.x, w0.x, fmaf(x4.y, w0.y, fmaf(x4.z, w0.z, fmaf(x4.w, w0.w, b4.x))));
    y4.y = fmaf(x4.x, w1.x, fmaf(x4.y, w1.y, fmaf(x4.z, w1.z, fmaf(x4.w, w1.w, b4.y))));
    y4.z = fmaf(x4.x, w2.x, fmaf(x4.y, w2.y, fmaf(x4.z, w2.z, fmaf(x4.w, w2.w, b4.z))));
    y4.w = fmaf(x4.x, w3.x, fmaf(x4.y, w3.y, fmaf(x4.z, w3.z, fmaf(x4.w, w3.w, b4.w))));

    // Slice: (S >> split_shift) * 128 float4, contiguous, 256-aligned start
    // (launcher guarantees S >> shift is even -> slice length multiple of
    // 256). Hence (i & 127) == d4 on every iteration: the same register-
    // resident float4 is streamed; each warp store is 512B contiguous.
    const int slice4 = (S >> split_shift) * 128;
    float4* out4 = reinterpret_cast<float4*>(out)
                 + (size_t)bt * (size_t)S * 128u
                 + (size_t)part * (size_t)slice4;

    #pragma unroll 4
    for (int i = tid; i < slice4; i += 256) {
        __stcs(out4 + i, y4);   // evict-first streaming store
    }
}

extern "C" void kernel_launch(void* const* d_in, const int* in_sizes, int n_in,
                              void* d_out, int out_size)
{
    // Inputs: x [B,T,4] f32, S (scalar), W [512,4] f32, b [512] f32.
    const float* x = (const float*)d_in[0];
    const float* W = (const float*)d_in[2];
    const float* b = (const float*)d_in[3];
    float* out = (float*)d_out;

    const int BT = in_sizes[0] / 4;          // B*T rows (d_inp = 4)
    const int S  = out_size / (BT * 512);    // recover S arithmetically

    // split=4 when S/4 is even (preserves the 256-float4 alignment
    // invariant); degrade gracefully otherwise. S=64 -> shift=2, grid 12288.
    int shift = 0;
    if      ((S % 8) == 0) shift = 2;
    else if ((S % 4) == 0) shift = 1;

    tfe_broadcast_kernel<<<BT << shift, 256>>>(x, W, b, out, S, shift);
}